// round 1
// baseline (speedup 1.0000x reference)
#include <cuda_runtime.h>
#include <cstdint>
#include <cstddef>

// Problem constants (fixed by the reference)
#define NN   100000     // nodes
#define NE   1600000    // edges
#define DD   128        // feature dim
#define DOUT 40         // output classes
#define NLAYERS 3

// ---------------------------------------------------------------------------
// Scratch (device globals — no runtime allocation allowed)
// ---------------------------------------------------------------------------
__device__ float g_h[(size_t)NN * DD];      // hidden state between layers
__device__ float g_prop[(size_t)NN * DD];   // scatter-add accumulator / post1 out
__device__ int   g_idx64;                   // 1 if edge_index is int64, 0 if int32

// ---------------------------------------------------------------------------
// Detect whether edge_index arrived as int64 or int32.
// If the data is really int32, reading it as int64 combines two indices:
// value = lo + hi*2^32 with hi in [0, NN) -> almost surely >= NN.
// Probability of a false "int64" verdict over 32 probes is ~1e-160.
// Runs inside the captured graph; deterministic for fixed input.
// ---------------------------------------------------------------------------
__global__ void detect_kernel(const int* __restrict__ ei)
{
    if (blockIdx.x == 0 && threadIdx.x == 0) {
        const long long* e64 = (const long long*)ei;
        int ok = 1;
        #pragma unroll 1
        for (int i = 0; i < 16; i++) {
            long long s = e64[i];
            long long d = e64[NE + i];
            if (s < 0 || s >= NN || d < 0 || d >= NN) ok = 0;
        }
        g_idx64 = ok;
    }
}

// ---------------------------------------------------------------------------
// Zero the propagation accumulator (float4 granularity)
// ---------------------------------------------------------------------------
__global__ void zero_kernel(float4* __restrict__ p, int n4)
{
    int i = blockIdx.x * blockDim.x + threadIdx.x;
    if (i < n4) p[i] = make_float4(0.f, 0.f, 0.f, 0.f);
}

// ---------------------------------------------------------------------------
// Scatter-add: prop[dst] += h[src]  over all edges.
// One warp per edge; each lane moves a float4 (32 lanes * 16B = 512B row).
// Vector reduction (red.global.add.v4.f32, sm_90+) = 1 atomic op per lane.
// h and prop are L2-resident (51.2MB each vs 126MB L2).
// ---------------------------------------------------------------------------
__global__ void scatter_kernel(const float* __restrict__ h,
                               const int*   __restrict__ ei,
                               float*       __restrict__ prop)
{
    int w    = (int)((blockIdx.x * blockDim.x + threadIdx.x) >> 5);
    int lane = threadIdx.x & 31;
    if (w >= NE) return;

    int src, dst;
    if (g_idx64) {
        const long long* e64 = (const long long*)ei;
        src = (int)e64[w];
        dst = (int)e64[NE + w];
    } else {
        src = ei[w];
        dst = ei[NE + w];
    }

    float4 v = *(const float4*)(h + (size_t)src * DD + lane * 4);
    float* p = prop + (size_t)dst * DD + lane * 4;
    asm volatile("red.global.add.v4.f32 [%0], {%1, %2, %3, %4};"
                 :: "l"(p), "f"(v.x), "f"(v.y), "f"(v.z), "f"(v.w)
                 : "memory");
}

// ---------------------------------------------------------------------------
// Fused GEMM:
//   NSEG==2: out = A0 @ B0^T + A1 @ B1^T + (bias0 + bias1)   (layer step)
//   NSEG==1: out = A0 @ B0^T + bias0                          (post1)
// A*: [NN, 128] row-major.  B*: [128, 128] row-major (out_feat, in_feat).
// NORMRELU: L2-normalize each output row (eps=1e-12) then ReLU.
// Tile: 128 rows x 128 cols per block, 256 threads, 8x8 microtile/thread.
// ---------------------------------------------------------------------------
template<int NSEG, bool NORMRELU>
__global__ void __launch_bounds__(256)
gemm_kernel(const float* __restrict__ A0, const float* __restrict__ A1,
            const float* __restrict__ B0, const float* __restrict__ B1,
            const float* __restrict__ bias0, const float* __restrict__ bias1,
            float* __restrict__ out)
{
    __shared__ float As[16][132];   // [k][m], padded
    __shared__ float Bs[16][132];   // [k][o], padded
    __shared__ float bsh[128];

    const int tid = threadIdx.x;
    const int tx  = tid & 15;       // output-feature group (8 cols each)
    const int ty  = tid >> 4;       // row group (8 rows each)
    const int n0  = blockIdx.x * 128;

    if (tid < 128) {
        float b = bias0[tid];
        if (NSEG == 2) b += bias1[tid];
        bsh[tid] = b;
    }

    float acc[8][8];
    #pragma unroll
    for (int i = 0; i < 8; i++)
        #pragma unroll
        for (int j = 0; j < 8; j++)
            acc[i][j] = 0.f;

    #pragma unroll 1
    for (int t = 0; t < NSEG * 8; t++) {
        const int seg = t >> 3;
        const int kk  = (t & 7) * 16;
        const float* A = (NSEG == 2 && seg) ? A1 : A0;
        const float* B = (NSEG == 2 && seg) ? B1 : B0;

        __syncthreads();
        #pragma unroll
        for (int r = 0; r < 2; r++) {
            int idx = tid + r * 256;        // 0..511
            int m   = idx >> 2;             // 0..127
            int kq  = idx & 3;              // float4 index along k
            int grow = n0 + m;
            float4 v = make_float4(0.f, 0.f, 0.f, 0.f);
            if (grow < NN)
                v = *(const float4*)(A + (size_t)grow * DD + kk + kq * 4);
            As[kq*4+0][m] = v.x; As[kq*4+1][m] = v.y;
            As[kq*4+2][m] = v.z; As[kq*4+3][m] = v.w;

            float4 w = *(const float4*)(B + (size_t)m * DD + kk + kq * 4);
            Bs[kq*4+0][m] = w.x; Bs[kq*4+1][m] = w.y;
            Bs[kq*4+2][m] = w.z; Bs[kq*4+3][m] = w.w;
        }
        __syncthreads();

        #pragma unroll
        for (int k = 0; k < 16; k++) {
            float a[8], b[8];
            *(float4*)&a[0] = *(const float4*)&As[k][ty * 8];
            *(float4*)&a[4] = *(const float4*)&As[k][ty * 8 + 4];
            *(float4*)&b[0] = *(const float4*)&Bs[k][tx * 8];
            *(float4*)&b[4] = *(const float4*)&Bs[k][tx * 8 + 4];
            #pragma unroll
            for (int i = 0; i < 8; i++)
                #pragma unroll
                for (int j = 0; j < 8; j++)
                    acc[i][j] = fmaf(a[i], b[j], acc[i][j]);
        }
    }

    // -------- epilogue --------
    float bv[8];
    #pragma unroll
    for (int j = 0; j < 8; j++) bv[j] = bsh[tx * 8 + j];

    #pragma unroll
    for (int i = 0; i < 8; i++) {
        int grow = n0 + ty * 8 + i;
        float v[8];
        if (NORMRELU) {
            float ss = 0.f;
            #pragma unroll
            for (int j = 0; j < 8; j++) {
                v[j] = acc[i][j] + bv[j];
                ss += v[j] * v[j];
            }
            // reduce across the 16 threads (same ty) holding this row
            #pragma unroll
            for (int d = 1; d < 16; d <<= 1)
                ss += __shfl_xor_sync(0xffffffffu, ss, d);
            float inv = 1.0f / fmaxf(sqrtf(ss), 1e-12f);
            #pragma unroll
            for (int j = 0; j < 8; j++)
                v[j] = fmaxf(v[j] * inv, 0.f);
        } else {
            #pragma unroll
            for (int j = 0; j < 8; j++)
                v[j] = acc[i][j] + bv[j];
        }
        if (grow < NN) {
            *(float4*)(out + (size_t)grow * DD + tx * 8)     = *(float4*)&v[0];
            *(float4*)(out + (size_t)grow * DD + tx * 8 + 4) = *(float4*)&v[4];
        }
    }
}

// ---------------------------------------------------------------------------
// post2 + log_softmax: out[n,:] = log_softmax(h[n,:] @ W^T + b), DOUT=40, K=128
// Thread-per-node; W staged in shared (broadcast reads).
// ---------------------------------------------------------------------------
__global__ void __launch_bounds__(256)
post2_kernel(const float* __restrict__ h, const float* __restrict__ W,
             const float* __restrict__ b, float* __restrict__ out)
{
    __shared__ float Ws[DOUT * DD];
    __shared__ float bs[DOUT];
    const int tid = threadIdx.x;
    for (int i = tid; i < DOUT * DD; i += blockDim.x) Ws[i] = W[i];
    if (tid < DOUT) bs[tid] = b[tid];
    __syncthreads();

    int n = blockIdx.x * blockDim.x + tid;
    if (n >= NN) return;

    float acc[DOUT];
    #pragma unroll
    for (int o = 0; o < DOUT; o++) acc[o] = bs[o];

    const float4* row = (const float4*)(h + (size_t)n * DD);
    #pragma unroll 1
    for (int kq = 0; kq < DD / 4; kq++) {
        float4 x = row[kq];
        #pragma unroll
        for (int o = 0; o < DOUT; o++) {
            const float* wr = &Ws[o * DD + kq * 4];
            acc[o] = fmaf(x.x, wr[0], acc[o]);
            acc[o] = fmaf(x.y, wr[1], acc[o]);
            acc[o] = fmaf(x.z, wr[2], acc[o]);
            acc[o] = fmaf(x.w, wr[3], acc[o]);
        }
    }

    float m = acc[0];
    #pragma unroll
    for (int o = 1; o < DOUT; o++) m = fmaxf(m, acc[o]);
    float s = 0.f;
    #pragma unroll
    for (int o = 0; o < DOUT; o++) s += expf(acc[o] - m);
    float ls = logf(s);
    #pragma unroll
    for (int o = 0; o < DOUT; o++)
        out[(size_t)n * DOUT + o] = acc[o] - m - ls;
}

// ---------------------------------------------------------------------------
// Launcher (graph-capturable: kernel launches only, default stream)
// Inputs: x, edge_index, Wl, bl, Wr, br, W_post1, b_post1, W_post2, b_post2
// ---------------------------------------------------------------------------
extern "C" void kernel_launch(void* const* d_in, const int* in_sizes, int n_in,
                              void* d_out, int out_size)
{
    const float* x   = (const float*)d_in[0];
    const int*   ei  = (const int*)  d_in[1];   // width resolved on-device
    const float* Wl  = (const float*)d_in[2];
    const float* bl  = (const float*)d_in[3];
    const float* Wr  = (const float*)d_in[4];
    const float* br  = (const float*)d_in[5];
    const float* Wp1 = (const float*)d_in[6];
    const float* bp1 = (const float*)d_in[7];
    const float* Wp2 = (const float*)d_in[8];
    const float* bp2 = (const float*)d_in[9];
    float* out = (float*)d_out;

    float *h, *prop;
    cudaGetSymbolAddress((void**)&h,    g_h);
    cudaGetSymbolAddress((void**)&prop, g_prop);

    detect_kernel<<<1, 1>>>(ei);

    const int n4          = NN * DD / 4;                 // 3.2M float4
    const int zero_blocks = (n4 + 255) / 256;            // 12500
    const int scat_blocks = NE / 8;                      // 8 warps/block -> 200000
    const int gemm_blocks = (NN + 127) / 128;            // 782

    for (int l = 0; l < NLAYERS; l++) {
        const float* hin = (l == 0) ? x : h;
        zero_kernel<<<zero_blocks, 256>>>((float4*)prop, n4);
        scatter_kernel<<<scat_blocks, 256>>>(hin, ei, prop);
        gemm_kernel<2, true><<<gemm_blocks, 256>>>(
            hin, prop,
            Wl + (size_t)l * DD * DD, Wr + (size_t)l * DD * DD,
            bl + (size_t)l * DD,      br + (size_t)l * DD,
            h);
    }

    // post1: [NN,128] = h @ Wp1^T + bp1  -> reuse prop as scratch
    gemm_kernel<1, false><<<gemm_blocks, 256>>>(
        h, nullptr, Wp1, nullptr, bp1, nullptr, prop);

    // post2 + log_softmax -> d_out
    post2_kernel<<<(NN + 255) / 256, 256>>>(prop, Wp2, bp2, out);
}

// round 2
// speedup vs baseline: 1.3906x; 1.3906x over previous
#include <cuda_runtime.h>
#include <cstdint>
#include <cstddef>

#define NN   100000
#define NE   1600000
#define DD   128
#define DOUT 40
#define NLAYERS 3
#define NBLK ((NN + 255) / 256)   // 391 blocks for node-wise 256-thread passes

// ---------------------------------------------------------------------------
// Scratch (device globals — no runtime allocation allowed)
// ---------------------------------------------------------------------------
__device__ float g_h[(size_t)NN * DD];
__device__ float g_prop[(size_t)NN * DD];
__device__ float g_tmp[(size_t)NN * DD];
__device__ int   g_deg[NN];
__device__ int   g_off[NN];
__device__ int   g_cur[NN];
__device__ int   g_csr[NE];
__device__ int   g_bsum[512];
__device__ int   g_boff[512];
__device__ int   g_idx64;

// ---------------------------------------------------------------------------
// int64 vs int32 edge-index detection (on-device, deterministic)
// ---------------------------------------------------------------------------
__global__ void detect_kernel(const int* __restrict__ ei)
{
    if (threadIdx.x == 0) {
        const long long* e64 = (const long long*)ei;
        int ok = 1;
        #pragma unroll 1
        for (int i = 0; i < 16; i++) {
            long long s = e64[i];
            long long d = e64[NE + i];
            if (s < 0 || s >= NN || d < 0 || d >= NN) ok = 0;
        }
        g_idx64 = ok;
    }
}

__device__ __forceinline__ int load_src(const int* ei, int e, int idx64)
{
    return idx64 ? (int)((const long long*)ei)[e] : ei[e];
}
__device__ __forceinline__ int load_dst(const int* ei, int e, int idx64)
{
    return idx64 ? (int)((const long long*)ei)[NE + e] : ei[NE + e];
}

// ---------------------------------------------------------------------------
// CSR build: zero deg -> count -> 3-pass exclusive scan -> fill
// ---------------------------------------------------------------------------
__global__ void zero_deg_kernel()
{
    int i = blockIdx.x * blockDim.x + threadIdx.x;
    if (i < NN) g_deg[i] = 0;
}

__global__ void count_kernel(const int* __restrict__ ei)
{
    int e = blockIdx.x * blockDim.x + threadIdx.x;
    if (e < NE) {
        int dst = load_dst(ei, e, g_idx64);
        atomicAdd(&g_deg[dst], 1);
    }
}

// pass A: per-block sums of degree
__global__ void scanA_kernel()
{
    __shared__ int s[256];
    int i = blockIdx.x * 256 + threadIdx.x;
    int v = (i < NN) ? g_deg[i] : 0;
    s[threadIdx.x] = v;
    __syncthreads();
    for (int d = 128; d > 0; d >>= 1) {
        if (threadIdx.x < d) s[threadIdx.x] += s[threadIdx.x + d];
        __syncthreads();
    }
    if (threadIdx.x == 0) g_bsum[blockIdx.x] = s[0];
}

// pass B: single-block exclusive scan of the block sums (NBLK <= 512)
__global__ void scanB_kernel()
{
    __shared__ int s[512];
    int tid = threadIdx.x;
    int v = (tid < NBLK) ? g_bsum[tid] : 0;
    s[tid] = v;
    __syncthreads();
    for (int d = 1; d < 512; d <<= 1) {
        int t = (tid >= d) ? s[tid - d] : 0;
        __syncthreads();
        s[tid] += t;
        __syncthreads();
    }
    if (tid < NBLK) g_boff[tid] = s[tid] - v;   // exclusive
}

// pass C: per-block local exclusive scan + block offset -> offsets & cursors
__global__ void scanC_kernel()
{
    __shared__ int s[256];
    int i = blockIdx.x * 256 + threadIdx.x;
    int v = (i < NN) ? g_deg[i] : 0;
    s[threadIdx.x] = v;
    __syncthreads();
    for (int d = 1; d < 256; d <<= 1) {
        int t = (threadIdx.x >= d) ? s[threadIdx.x - d] : 0;
        __syncthreads();
        s[threadIdx.x] += t;
        __syncthreads();
    }
    if (i < NN) {
        int off = g_boff[blockIdx.x] + s[threadIdx.x] - v;   // exclusive
        g_off[i] = off;
        g_cur[i] = off;
    }
}

__global__ void fill_kernel(const int* __restrict__ ei)
{
    int e = blockIdx.x * blockDim.x + threadIdx.x;
    if (e < NE) {
        int idx64 = g_idx64;
        int src = load_src(ei, e, idx64);
        int dst = load_dst(ei, e, idx64);
        int p = atomicAdd(&g_cur[dst], 1);
        g_csr[p] = src;
    }
}

// ---------------------------------------------------------------------------
// Gather aggregation: prop[d] = sum over in-edges of h[src]. One warp per dst
// node, each lane owns a float4 (32 x 16B = 512B row). No atomics, no zeroing.
// ---------------------------------------------------------------------------
__global__ void __launch_bounds__(256)
gather_kernel(const float* __restrict__ h, float* __restrict__ prop)
{
    int d    = blockIdx.x * 8 + (threadIdx.x >> 5);
    int lane = threadIdx.x & 31;
    if (d >= NN) return;

    int off = g_off[d];
    int deg = g_deg[d];
    float4 acc = make_float4(0.f, 0.f, 0.f, 0.f);

    int j = 0;
    for (; j + 2 <= deg; j += 2) {
        int s0 = g_csr[off + j];
        int s1 = g_csr[off + j + 1];
        float4 a = *(const float4*)(h + (size_t)s0 * DD + lane * 4);
        float4 b = *(const float4*)(h + (size_t)s1 * DD + lane * 4);
        acc.x += a.x + b.x; acc.y += a.y + b.y;
        acc.z += a.z + b.z; acc.w += a.w + b.w;
    }
    if (j < deg) {
        int s0 = g_csr[off + j];
        float4 a = *(const float4*)(h + (size_t)s0 * DD + lane * 4);
        acc.x += a.x; acc.y += a.y; acc.z += a.z; acc.w += a.w;
    }
    *(float4*)(prop + (size_t)d * DD + lane * 4) = acc;
}

// ---------------------------------------------------------------------------
// SGEMM: out = A @ B^T + bias [+ addin] [then L2-normalize rows + ReLU]
// A: [NN,128] row-major, B: [128,128] row-major (out_feat, in_feat), K=128.
// 128x128 tile / block, 256 threads, 8x8 microtile. At fp32 FFMA ceiling.
// ---------------------------------------------------------------------------
template<bool ADD_IN, bool NORMRELU>
__global__ void __launch_bounds__(256)
gemm_kernel(const float* __restrict__ A, const float* __restrict__ B,
            const float* __restrict__ bias, const float* __restrict__ addin,
            float* __restrict__ out)
{
    __shared__ float As[16][132];
    __shared__ float Bs[16][132];
    __shared__ float bsh[128];

    const int tid = threadIdx.x;
    const int tx  = tid & 15;
    const int ty  = tid >> 4;
    const int n0  = blockIdx.x * 128;

    if (tid < 128) bsh[tid] = bias[tid];

    float acc[8][8];
    #pragma unroll
    for (int i = 0; i < 8; i++)
        #pragma unroll
        for (int j = 0; j < 8; j++)
            acc[i][j] = 0.f;

    #pragma unroll 1
    for (int t = 0; t < 8; t++) {
        const int kk = t * 16;
        __syncthreads();
        #pragma unroll
        for (int r = 0; r < 2; r++) {
            int idx = tid + r * 256;
            int m   = idx >> 2;
            int kq  = idx & 3;
            int grow = n0 + m;
            float4 v = make_float4(0.f, 0.f, 0.f, 0.f);
            if (grow < NN)
                v = *(const float4*)(A + (size_t)grow * DD + kk + kq * 4);
            As[kq*4+0][m] = v.x; As[kq*4+1][m] = v.y;
            As[kq*4+2][m] = v.z; As[kq*4+3][m] = v.w;

            float4 w = *(const float4*)(B + (size_t)m * DD + kk + kq * 4);
            Bs[kq*4+0][m] = w.x; Bs[kq*4+1][m] = w.y;
            Bs[kq*4+2][m] = w.z; Bs[kq*4+3][m] = w.w;
        }
        __syncthreads();

        #pragma unroll
        for (int k = 0; k < 16; k++) {
            float a[8], b[8];
            *(float4*)&a[0] = *(const float4*)&As[k][ty * 8];
            *(float4*)&a[4] = *(const float4*)&As[k][ty * 8 + 4];
            *(float4*)&b[0] = *(const float4*)&Bs[k][tx * 8];
            *(float4*)&b[4] = *(const float4*)&Bs[k][tx * 8 + 4];
            #pragma unroll
            for (int i = 0; i < 8; i++)
                #pragma unroll
                for (int j = 0; j < 8; j++)
                    acc[i][j] = fmaf(a[i], b[j], acc[i][j]);
        }
    }

    float bv[8];
    #pragma unroll
    for (int j = 0; j < 8; j++) bv[j] = bsh[tx * 8 + j];

    #pragma unroll
    for (int i = 0; i < 8; i++) {
        int grow = n0 + ty * 8 + i;
        if (grow >= NN) continue;
        float v[8];
        #pragma unroll
        for (int j = 0; j < 8; j++) v[j] = acc[i][j] + bv[j];

        if (ADD_IN) {
            float4 a0 = *(const float4*)(addin + (size_t)grow * DD + tx * 8);
            float4 a1 = *(const float4*)(addin + (size_t)grow * DD + tx * 8 + 4);
            v[0] += a0.x; v[1] += a0.y; v[2] += a0.z; v[3] += a0.w;
            v[4] += a1.x; v[5] += a1.y; v[6] += a1.z; v[7] += a1.w;
        }
        if (NORMRELU) {
            float ss = 0.f;
            #pragma unroll
            for (int j = 0; j < 8; j++) ss += v[j] * v[j];
            #pragma unroll
            for (int d = 1; d < 16; d <<= 1)
                ss += __shfl_xor_sync(0xffffffffu, ss, d);
            float inv = 1.0f / fmaxf(sqrtf(ss), 1e-12f);
            #pragma unroll
            for (int j = 0; j < 8; j++)
                v[j] = fmaxf(v[j] * inv, 0.f);
        }
        *(float4*)(out + (size_t)grow * DD + tx * 8)     = *(float4*)&v[0];
        *(float4*)(out + (size_t)grow * DD + tx * 8 + 4) = *(float4*)&v[4];
    }
}

// ---------------------------------------------------------------------------
// post2 + log_softmax
// ---------------------------------------------------------------------------
__global__ void __launch_bounds__(256)
post2_kernel(const float* __restrict__ h, const float* __restrict__ W,
             const float* __restrict__ b, float* __restrict__ out)
{
    __shared__ float Ws[DOUT * DD];
    __shared__ float bs[DOUT];
    const int tid = threadIdx.x;
    for (int i = tid; i < DOUT * DD; i += blockDim.x) Ws[i] = W[i];
    if (tid < DOUT) bs[tid] = b[tid];
    __syncthreads();

    int n = blockIdx.x * blockDim.x + tid;
    if (n >= NN) return;

    float acc[DOUT];
    #pragma unroll
    for (int o = 0; o < DOUT; o++) acc[o] = bs[o];

    const float4* row = (const float4*)(h + (size_t)n * DD);
    #pragma unroll 1
    for (int kq = 0; kq < DD / 4; kq++) {
        float4 x = row[kq];
        #pragma unroll
        for (int o = 0; o < DOUT; o++) {
            const float* wr = &Ws[o * DD + kq * 4];
            acc[o] = fmaf(x.x, wr[0], acc[o]);
            acc[o] = fmaf(x.y, wr[1], acc[o]);
            acc[o] = fmaf(x.z, wr[2], acc[o]);
            acc[o] = fmaf(x.w, wr[3], acc[o]);
        }
    }

    float m = acc[0];
    #pragma unroll
    for (int o = 1; o < DOUT; o++) m = fmaxf(m, acc[o]);
    float s = 0.f;
    #pragma unroll
    for (int o = 0; o < DOUT; o++) s += expf(acc[o] - m);
    float ls = logf(s);
    #pragma unroll
    for (int o = 0; o < DOUT; o++)
        out[(size_t)n * DOUT + o] = acc[o] - m - ls;
}

// ---------------------------------------------------------------------------
// Static stream/event resources (created at module load, before any memory
// checkpoint; no device-memory allocation involved)
// ---------------------------------------------------------------------------
struct GpuRes {
    cudaStream_t s2;
    cudaEvent_t  evF, evP, evH;
    GpuRes() {
        cudaStreamCreateWithFlags(&s2, cudaStreamNonBlocking);
        cudaEventCreateWithFlags(&evF, cudaEventDisableTiming);
        cudaEventCreateWithFlags(&evP, cudaEventDisableTiming);
        cudaEventCreateWithFlags(&evH, cudaEventDisableTiming);
    }
};
static GpuRes g_res;

// ---------------------------------------------------------------------------
// Launcher. Dataflow per layer l:
//   s2: gather_l (CSR aggregation, L2-bound)   } overlap
//   s0: gemm1_l  (h @ Wl, compute-bound)       }
//   s0: (wait gather) gemm2_l = tmp + prop@Wr + bias, normalize+relu -> h
// CSR build (s2) overlaps with layer-0 gemm1 (x @ Wl0).
// ---------------------------------------------------------------------------
extern "C" void kernel_launch(void* const* d_in, const int* in_sizes, int n_in,
                              void* d_out, int out_size)
{
    const float* x   = (const float*)d_in[0];
    const int*   ei  = (const int*)  d_in[1];
    const float* Wl  = (const float*)d_in[2];
    const float* bl  = (const float*)d_in[3];
    const float* Wr  = (const float*)d_in[4];
    const float* br  = (const float*)d_in[5];
    const float* Wp1 = (const float*)d_in[6];
    const float* bp1 = (const float*)d_in[7];
    const float* Wp2 = (const float*)d_in[8];
    const float* bp2 = (const float*)d_in[9];
    float* out = (float*)d_out;

    float *h, *prop, *tmp;
    cudaGetSymbolAddress((void**)&h,    g_h);
    cudaGetSymbolAddress((void**)&prop, g_prop);
    cudaGetSymbolAddress((void**)&tmp,  g_tmp);

    cudaStream_t s0 = 0;
    cudaStream_t s2 = g_res.s2;

    // Fork s2 off the capture stream
    detect_kernel<<<1, 1, 0, s0>>>(ei);
    cudaEventRecord(g_res.evF, s0);
    cudaStreamWaitEvent(s2, g_res.evF, 0);

    // CSR build on s2 (overlaps layer-0 gemm1 on s0)
    zero_deg_kernel<<<NBLK, 256, 0, s2>>>();
    count_kernel<<<(NE + 255) / 256, 256, 0, s2>>>(ei);
    scanA_kernel<<<NBLK, 256, 0, s2>>>();
    scanB_kernel<<<1, 512, 0, s2>>>();
    scanC_kernel<<<NBLK, 256, 0, s2>>>();
    fill_kernel<<<(NE + 255) / 256, 256, 0, s2>>>(ei);

    const int GB  = (NN + 127) / 128;       // 782 gemm blocks
    const int GGB = (NN + 7) / 8;           // 12500 gather blocks

    for (int l = 0; l < NLAYERS; l++) {
        const float* hin = (l == 0) ? x : h;

        if (l > 0) cudaStreamWaitEvent(s2, g_res.evH, 0);
        gather_kernel<<<GGB, 256, 0, s2>>>(hin, prop);
        cudaEventRecord(g_res.evP, s2);

        // gemm1 (independent of gather) — launched on s0 without waiting
        gemm_kernel<false, false><<<GB, 256, 0, s0>>>(
            hin, Wl + (size_t)l * DD * DD, bl + (size_t)l * DD, nullptr, tmp);

        cudaStreamWaitEvent(s0, g_res.evP, 0);
        gemm_kernel<true, true><<<GB, 256, 0, s0>>>(
            prop, Wr + (size_t)l * DD * DD, br + (size_t)l * DD, tmp, h);
        cudaEventRecord(g_res.evH, s0);
    }

    // post1 -> prop scratch, then post2 + log_softmax -> out
    gemm_kernel<false, false><<<GB, 256, 0, s0>>>(h, Wp1, bp1, nullptr, prop);
    post2_kernel<<<NBLK, 256, 0, s0>>>(prop, Wp2, bp2, out);
}

// round 4
// speedup vs baseline: 1.4753x; 1.0608x over previous
#include <cuda_runtime.h>
#include <cuda_bf16.h>
#include <cstdint>
#include <cstddef>

#define NN   100000
#define NE   1600000
#define DD   128
#define DOUT 40
#define NLAYERS 3
#define NBLK ((NN + 255) / 256)
#define GTILES ((NN + 127) / 128)

// ---------------------------------------------------------------------------
// Device scratch (no runtime allocation allowed)
// ---------------------------------------------------------------------------
__device__ float g_h[(size_t)NN * DD];
__device__ float g_prop[(size_t)NN * DD];
__device__ int g_deg[NN], g_off[NN], g_cur[NN], g_csr[NE];
__device__ int g_bsum[512], g_boff[512], g_idx64;

// ---------------------------------------------------------------------------
// MMA helpers (base PTX ISA, valid on compute_100 virtual arch)
// ---------------------------------------------------------------------------
__device__ __forceinline__ uint32_t smem_u32(const void* p) {
    uint32_t a;
    asm("{ .reg .u64 t; cvta.to.shared.u64 t, %1; cvt.u32.u64 %0, t; }"
        : "=r"(a) : "l"(p));
    return a;
}
#define LDSM4(r0, r1, r2, r3, addr) \
    asm volatile("ldmatrix.sync.aligned.m8n8.x4.shared.b16 {%0,%1,%2,%3}, [%4];" \
                 : "=r"(r0), "=r"(r1), "=r"(r2), "=r"(r3) : "r"(addr))
#define MMA16816(c, a, b) \
    asm volatile("mma.sync.aligned.m16n8k16.row.col.f32.bf16.bf16.f32 " \
                 "{%0,%1,%2,%3},{%4,%5,%6,%7},{%8,%9},{%0,%1,%2,%3};" \
                 : "+f"((c)[0]), "+f"((c)[1]), "+f"((c)[2]), "+f"((c)[3]) \
                 : "r"((a)[0]), "r"((a)[1]), "r"((a)[2]), "r"((a)[3]), \
                   "r"((b)[0]), "r"((b)[1]))

// SMEM plan for the mma kernel (bytes). Row stride 136 bf16 = 272B
// (16B-aligned rows; rotated bank groups -> ldmatrix conflict-free).
#define SM_AHI  0
#define SM_ALO  34816
#define SM_WHI  69632
#define SM_WLO  104448
#define SM_BIAS 139264
#define SM_TOTAL 139776

// split one float4 into hi/lo bf16 planes at [row][q*4]
__device__ __forceinline__ void split_store(char* smem, int hiOff, int loOff,
                                            int row, int q, float4 v)
{
    __nv_bfloat16 h0 = __float2bfloat16_rn(v.x);
    __nv_bfloat16 h1 = __float2bfloat16_rn(v.y);
    __nv_bfloat16 h2 = __float2bfloat16_rn(v.z);
    __nv_bfloat16 h3 = __float2bfloat16_rn(v.w);
    float r0 = v.x - __bfloat162float(h0);
    float r1 = v.y - __bfloat162float(h1);
    float r2 = v.z - __bfloat162float(h2);
    float r3 = v.w - __bfloat162float(h3);
    __nv_bfloat16 l0 = __float2bfloat16_rn(r0);
    __nv_bfloat16 l1 = __float2bfloat16_rn(r1);
    __nv_bfloat16 l2 = __float2bfloat16_rn(r2);
    __nv_bfloat16 l3 = __float2bfloat16_rn(r3);
    uint32_t hi01 = (uint32_t)__bfloat16_as_ushort(h0) | ((uint32_t)__bfloat16_as_ushort(h1) << 16);
    uint32_t hi23 = (uint32_t)__bfloat16_as_ushort(h2) | ((uint32_t)__bfloat16_as_ushort(h3) << 16);
    uint32_t lo01 = (uint32_t)__bfloat16_as_ushort(l0) | ((uint32_t)__bfloat16_as_ushort(l1) << 16);
    uint32_t lo23 = (uint32_t)__bfloat16_as_ushort(l2) | ((uint32_t)__bfloat16_as_ushort(l3) << 16);
    uint32_t off = (uint32_t)(row * 272 + q * 8);
    *(uint2*)(smem + hiOff + off) = make_uint2(hi01, hi23);
    *(uint2*)(smem + loOff + off) = make_uint2(lo01, lo23);
}

// ---------------------------------------------------------------------------
// int64 vs int32 edge-index detection
// ---------------------------------------------------------------------------
__global__ void detect_kernel(const int* __restrict__ ei)
{
    if (threadIdx.x == 0) {
        const long long* e64 = (const long long*)ei;
        int ok = 1;
        #pragma unroll 1
        for (int i = 0; i < 16; i++) {
            long long s = e64[i], d = e64[NE + i];
            if (s < 0 || s >= NN || d < 0 || d >= NN) ok = 0;
        }
        g_idx64 = ok;
    }
}
__device__ __forceinline__ int load_src(const int* ei, int e, int w) {
    return w ? (int)((const long long*)ei)[e] : ei[e];
}
__device__ __forceinline__ int load_dst(const int* ei, int e, int w) {
    return w ? (int)((const long long*)ei)[NE + e] : ei[NE + e];
}

// ---------------------------------------------------------------------------
// CSR build (proven in R2)
// ---------------------------------------------------------------------------
__global__ void zero_deg_kernel()
{
    int i = blockIdx.x * blockDim.x + threadIdx.x;
    if (i < NN) g_deg[i] = 0;
}
__global__ void count_kernel(const int* __restrict__ ei)
{
    int e = blockIdx.x * blockDim.x + threadIdx.x;
    if (e < NE) atomicAdd(&g_deg[load_dst(ei, e, g_idx64)], 1);
}
__global__ void scanA_kernel()
{
    __shared__ int s[256];
    int i = blockIdx.x * 256 + threadIdx.x;
    int v = (i < NN) ? g_deg[i] : 0;
    s[threadIdx.x] = v; __syncthreads();
    for (int d = 128; d > 0; d >>= 1) {
        if (threadIdx.x < d) s[threadIdx.x] += s[threadIdx.x + d];
        __syncthreads();
    }
    if (threadIdx.x == 0) g_bsum[blockIdx.x] = s[0];
}
__global__ void scanB_kernel()
{
    __shared__ int s[512];
    int tid = threadIdx.x;
    int v = (tid < NBLK) ? g_bsum[tid] : 0;
    s[tid] = v; __syncthreads();
    for (int d = 1; d < 512; d <<= 1) {
        int t = (tid >= d) ? s[tid - d] : 0;
        __syncthreads();
        s[tid] += t; __syncthreads();
    }
    if (tid < NBLK) g_boff[tid] = s[tid] - v;
}
__global__ void scanC_kernel()
{
    __shared__ int s[256];
    int i = blockIdx.x * 256 + threadIdx.x;
    int v = (i < NN) ? g_deg[i] : 0;
    s[threadIdx.x] = v; __syncthreads();
    for (int d = 1; d < 256; d <<= 1) {
        int t = (threadIdx.x >= d) ? s[threadIdx.x - d] : 0;
        __syncthreads();
        s[threadIdx.x] += t; __syncthreads();
    }
    if (i < NN) {
        int off = g_boff[blockIdx.x] + s[threadIdx.x] - v;
        g_off[i] = off; g_cur[i] = off;
    }
}
__global__ void fill_kernel(const int* __restrict__ ei)
{
    int e = blockIdx.x * blockDim.x + threadIdx.x;
    if (e < NE) {
        int w = g_idx64;
        int src = load_src(ei, e, w);
        int dst = load_dst(ei, e, w);
        g_csr[atomicAdd(&g_cur[dst], 1)] = src;
    }
}

// ---------------------------------------------------------------------------
// Gather aggregation (proven in R2): prop[d] = sum_{src in N(d)} h[src]
// ---------------------------------------------------------------------------
__global__ void __launch_bounds__(256)
gather_kernel(const float* __restrict__ h, float* __restrict__ prop)
{
    int d    = blockIdx.x * 8 + (threadIdx.x >> 5);
    int lane = threadIdx.x & 31;
    if (d >= NN) return;

    int off = g_off[d], deg = g_deg[d];
    float4 acc = make_float4(0.f, 0.f, 0.f, 0.f);

    int j = 0;
    for (; j + 4 <= deg; j += 4) {
        int s0 = g_csr[off + j],     s1 = g_csr[off + j + 1];
        int s2 = g_csr[off + j + 2], s3 = g_csr[off + j + 3];
        float4 a = *(const float4*)(h + (size_t)s0 * DD + lane * 4);
        float4 b = *(const float4*)(h + (size_t)s1 * DD + lane * 4);
        float4 c = *(const float4*)(h + (size_t)s2 * DD + lane * 4);
        float4 e = *(const float4*)(h + (size_t)s3 * DD + lane * 4);
        acc.x += (a.x + b.x) + (c.x + e.x);
        acc.y += (a.y + b.y) + (c.y + e.y);
        acc.z += (a.z + b.z) + (c.z + e.z);
        acc.w += (a.w + b.w) + (c.w + e.w);
    }
    for (; j < deg; j++) {
        float4 a = *(const float4*)(h + (size_t)g_csr[off + j] * DD + lane * 4);
        acc.x += a.x; acc.y += a.y; acc.z += a.z; acc.w += a.w;
    }
    *(float4*)(prop + (size_t)d * DD + lane * 4) = acc;
}

// ---------------------------------------------------------------------------
// Fused tensor-core GEMM via mma.sync bf16 with 3xBF16 split.
//   TWO:  D = A0@W0^T + A1@W1^T + (b0+b1)   then optional row-L2-norm + ReLU
//   else: D = A0@W0^T + b0
// A: fp32 [NN,128]; W: fp32 [128,128] row-major (out_feat, in_feat).
// CTA = 128 rows x 128 cols, 256 threads = 8 warps (warp tile 32x64).
// Per phase: load+split into hi/lo bf16 smem planes, 3 products x 8 k-steps.
// ---------------------------------------------------------------------------
template<bool TWO, bool NORM>
__global__ void __launch_bounds__(256, 1)
mma_kernel(const float* __restrict__ A0, const float* __restrict__ A1,
           const float* __restrict__ W0, const float* __restrict__ W1,
           const float* __restrict__ b0, const float* __restrict__ b1,
           float* __restrict__ out)
{
    extern __shared__ char smem[];
    const uint32_t sb = smem_u32(smem);
    const int tid   = threadIdx.x;
    const int lane  = tid & 31;
    const int wid   = tid >> 5;
    const int warpM = wid & 3;      // 4 warps over M
    const int warpN = wid >> 2;     // 2 warps over N
    const int n0    = blockIdx.x * 128;

    float* bsh = (float*)(smem + SM_BIAS);
    if (tid < 128) {
        float b = b0[tid];
        if (TWO) b += b1[tid];
        bsh[tid] = b;
    }

    float acc[2][8][4];
    #pragma unroll
    for (int mt = 0; mt < 2; mt++)
        #pragma unroll
        for (int nt = 0; nt < 8; nt++)
            #pragma unroll
            for (int r = 0; r < 4; r++)
                acc[mt][nt][r] = 0.f;

    // per-lane ldmatrix address offsets
    const int mat = lane >> 3, r8 = lane & 7;
    const uint32_t aLane = (uint32_t)((warpM * 32 + (mat & 1) * 8 + r8) * 272
                                      + ((mat >> 1) * 8) * 2);
    const uint32_t bLane = (uint32_t)((warpN * 64 + (mat >> 1) * 8 + r8) * 272
                                      + ((mat & 1) * 8) * 2);

    const int NPH = TWO ? 2 : 1;
    #pragma unroll 1
    for (int ph = 0; ph < NPH; ph++) {
        const float* A = (TWO && ph) ? A1 : A0;
        const float* W = (TWO && ph) ? W1 : W0;

        __syncthreads();
        // ---- load A (guarded) and W, split into hi/lo planes ----
        #pragma unroll 1
        for (int r = 0; r < 16; r++) {
            int gi = tid + r * 256;
            int row = gi >> 5, q = gi & 31;
            int grow = n0 + row;
            float4 va = (grow < NN)
                ? *(const float4*)(A + (size_t)grow * DD + q * 4)
                : make_float4(0.f, 0.f, 0.f, 0.f);
            split_store(smem, SM_AHI, SM_ALO, row, q, va);
            float4 vw = *(const float4*)(W + (size_t)row * DD + q * 4);
            split_store(smem, SM_WHI, SM_WLO, row, q, vw);
        }
        __syncthreads();

        // ---- 3 split products (hi*hi, hi*lo, lo*hi) ----
        #pragma unroll 1
        for (int pr = 0; pr < 3; pr++) {
            const uint32_t aBase = sb + ((pr == 2) ? SM_ALO : SM_AHI) + aLane;
            const uint32_t bBase = sb + ((pr == 1) ? SM_WLO : SM_WHI) + bLane;
            #pragma unroll
            for (int ks = 0; ks < 8; ks++) {
                const uint32_t kOff = ks * 32;       // 16 bf16 = 32B
                uint32_t af[2][4];
                LDSM4(af[0][0], af[0][1], af[0][2], af[0][3], aBase + kOff);
                LDSM4(af[1][0], af[1][1], af[1][2], af[1][3], aBase + kOff + 16 * 272);
                uint32_t bf[8][2];
                #pragma unroll
                for (int p = 0; p < 4; p++) {
                    LDSM4(bf[2*p][0], bf[2*p][1], bf[2*p+1][0], bf[2*p+1][1],
                          bBase + kOff + p * 16 * 272);
                }
                #pragma unroll
                for (int mt = 0; mt < 2; mt++)
                    #pragma unroll
                    for (int nt = 0; nt < 8; nt++)
                        MMA16816(acc[mt][nt], af[mt], bf[nt]);
            }
        }
    }

    // ---- epilogue: stage acc in smem (reuse A planes), then row pass ----
    __syncthreads();
    float* fbuf = (float*)smem;                 // [128][132] fp32, 67.6KB
    {
        int row0 = warpM * 32 + (lane >> 2);
        int col0 = warpN * 64 + (lane & 3) * 2;
        #pragma unroll
        for (int mt = 0; mt < 2; mt++)
            #pragma unroll
            for (int nt = 0; nt < 8; nt++) {
                int r = row0 + mt * 16, c = col0 + nt * 8;
                fbuf[r * 132 + c]           = acc[mt][nt][0];
                fbuf[r * 132 + c + 1]       = acc[mt][nt][1];
                fbuf[(r + 8) * 132 + c]     = acc[mt][nt][2];
                fbuf[(r + 8) * 132 + c + 1] = acc[mt][nt][3];
            }
    }
    __syncthreads();
    {
        int row  = tid >> 1, half = tid & 1;
        int grow = n0 + row;
        const float* frow = fbuf + row * 132 + half * 64;
        const float* brow = bsh + half * 64;
        float inv = 1.0f;
        if (NORM) {
            float ss = 0.f;
            #pragma unroll
            for (int c = 0; c < 64; c++) {
                float v = frow[c] + brow[c];
                ss += v * v;
            }
            ss += __shfl_xor_sync(0xffffffffu, ss, 1);
            inv = 1.0f / fmaxf(sqrtf(ss), 1e-12f);
        }
        if (grow < NN) {
            float* orow = out + (size_t)grow * DD + half * 64;
            #pragma unroll
            for (int c = 0; c < 64; c += 4) {
                float4 f = *(const float4*)(frow + c);
                float4 bv = *(const float4*)(brow + c);
                f.x += bv.x; f.y += bv.y; f.z += bv.z; f.w += bv.w;
                if (NORM) {
                    f.x = fmaxf(f.x * inv, 0.f);
                    f.y = fmaxf(f.y * inv, 0.f);
                    f.z = fmaxf(f.z * inv, 0.f);
                    f.w = fmaxf(f.w * inv, 0.f);
                }
                *(float4*)(orow + c) = f;
            }
        }
    }
}

// ---------------------------------------------------------------------------
// post2 + log_softmax (fp32)
// ---------------------------------------------------------------------------
__global__ void __launch_bounds__(256)
post2_kernel(const float* __restrict__ h, const float* __restrict__ W,
             const float* __restrict__ b, float* __restrict__ out)
{
    __shared__ float Ws[DOUT * DD];
    __shared__ float bs[DOUT];
    const int tid = threadIdx.x;
    for (int i = tid; i < DOUT * DD; i += blockDim.x) Ws[i] = W[i];
    if (tid < DOUT) bs[tid] = b[tid];
    __syncthreads();

    int n = blockIdx.x * blockDim.x + tid;
    if (n >= NN) return;

    float acc[DOUT];
    #pragma unroll
    for (int o = 0; o < DOUT; o++) acc[o] = bs[o];

    const float4* row = (const float4*)(h + (size_t)n * DD);
    #pragma unroll 1
    for (int kq = 0; kq < DD / 4; kq++) {
        float4 x = row[kq];
        #pragma unroll
        for (int o = 0; o < DOUT; o++) {
            const float* wr = &Ws[o * DD + kq * 4];
            acc[o] = fmaf(x.x, wr[0], acc[o]);
            acc[o] = fmaf(x.y, wr[1], acc[o]);
            acc[o] = fmaf(x.z, wr[2], acc[o]);
            acc[o] = fmaf(x.w, wr[3], acc[o]);
        }
    }
    float m = acc[0];
    #pragma unroll
    for (int o = 1; o < DOUT; o++) m = fmaxf(m, acc[o]);
    float s = 0.f;
    #pragma unroll
    for (int o = 0; o < DOUT; o++) s += expf(acc[o] - m);
    float ls = logf(s);
    #pragma unroll
    for (int o = 0; o < DOUT; o++)
        out[(size_t)n * DOUT + o] = acc[o] - m - ls;
}

// ---------------------------------------------------------------------------
// Launcher: serial on default stream (graph-capturable, launches only)
// ---------------------------------------------------------------------------
extern "C" void kernel_launch(void* const* d_in, const int* in_sizes, int n_in,
                              void* d_out, int out_size)
{
    const float* x   = (const float*)d_in[0];
    const int*   ei  = (const int*)  d_in[1];
    const float* Wl  = (const float*)d_in[2];
    const float* bl  = (const float*)d_in[3];
    const float* Wr  = (const float*)d_in[4];
    const float* br  = (const float*)d_in[5];
    const float* Wp1 = (const float*)d_in[6];
    const float* bp1 = (const float*)d_in[7];
    const float* Wp2 = (const float*)d_in[8];
    const float* bp2 = (const float*)d_in[9];
    float* out = (float*)d_out;

    cudaFuncSetAttribute(mma_kernel<true,  true>,
                         cudaFuncAttributeMaxDynamicSharedMemorySize, SM_TOTAL);
    cudaFuncSetAttribute(mma_kernel<false, false>,
                         cudaFuncAttributeMaxDynamicSharedMemorySize, SM_TOTAL);

    float *h, *prop;
    cudaGetSymbolAddress((void**)&h,    g_h);
    cudaGetSymbolAddress((void**)&prop, g_prop);

    detect_kernel<<<1, 1>>>(ei);
    zero_deg_kernel<<<NBLK, 256>>>();
    count_kernel<<<(NE + 255) / 256, 256>>>(ei);
    scanA_kernel<<<NBLK, 256>>>();
    scanB_kernel<<<1, 512>>>();
    scanC_kernel<<<NBLK, 256>>>();
    fill_kernel<<<(NE + 255) / 256, 256>>>(ei);

    const int GGB = (NN + 7) / 8;
    for (int l = 0; l < NLAYERS; l++) {
        const float* hin = (l == 0) ? x : h;
        gather_kernel<<<GGB, 256>>>(hin, prop);
        mma_kernel<true, true><<<GTILES, 256, SM_TOTAL>>>(
            hin, prop,
            Wl + (size_t)l * DD * DD, Wr + (size_t)l * DD * DD,
            bl + (size_t)l * DD,      br + (size_t)l * DD,
            h);
    }

    // post1 -> prop scratch, then post2 + log_softmax -> out
    mma_kernel<false, false><<<GTILES, 256, SM_TOTAL>>>(
        h, nullptr, Wp1, nullptr, bp1, nullptr, prop);
    post2_kernel<<<NBLK, 256>>>(prop, Wp2, bp2, out);
}

// round 5
// speedup vs baseline: 1.5976x; 1.0829x over previous
#include <cuda_runtime.h>
#include <cuda_bf16.h>
#include <cstdint>
#include <cstddef>

#define NN   100000
#define NE   1600000
#define DD   128
#define DOUT 40
#define NLAYERS 3
#define NBLK ((NN + 255) / 256)
#define GTILES ((NN + 127) / 128)
#define NW 7   // weight matrices: Wl0..2, Wr0..2, Wpost1

// ---------------------------------------------------------------------------
// Device scratch. All feature tensors stored as TWO bf16 planes (hi, lo):
// value ~= hi + lo, representation error 2^-18 relative.
// ---------------------------------------------------------------------------
__device__ __align__(16) uint16_t g_xhi[(size_t)NN * DD];
__device__ __align__(16) uint16_t g_xlo[(size_t)NN * DD];
__device__ __align__(16) uint16_t g_hhi[(size_t)NN * DD];
__device__ __align__(16) uint16_t g_hlo[(size_t)NN * DD];
__device__ __align__(16) uint16_t g_phi[(size_t)NN * DD];
__device__ __align__(16) uint16_t g_plo[(size_t)NN * DD];
__device__ __align__(16) uint16_t g_whi[(size_t)NW * DD * DD];
__device__ __align__(16) uint16_t g_wlo[(size_t)NW * DD * DD];
__device__ float g_tmp[(size_t)NN * DD];
__device__ int g_deg[NN], g_off[NN], g_cur[NN], g_csr[NE];
__device__ int g_bsum[512], g_boff[512], g_idx64;

// ---------------------------------------------------------------------------
// helpers
// ---------------------------------------------------------------------------
__device__ __forceinline__ uint32_t smem_u32(const void* p) {
    uint32_t a;
    asm("{ .reg .u64 t; cvta.to.shared.u64 t, %1; cvt.u32.u64 %0, t; }"
        : "=r"(a) : "l"(p));
    return a;
}
#define LDSM4(r0, r1, r2, r3, addr) \
    asm volatile("ldmatrix.sync.aligned.m8n8.x4.shared.b16 {%0,%1,%2,%3}, [%4];" \
                 : "=r"(r0), "=r"(r1), "=r"(r2), "=r"(r3) : "r"(addr))
#define MMA16816(c, a, b) \
    asm volatile("mma.sync.aligned.m16n8k16.row.col.f32.bf16.bf16.f32 " \
                 "{%0,%1,%2,%3},{%4,%5,%6,%7},{%8,%9},{%0,%1,%2,%3};" \
                 : "+f"((c)[0]), "+f"((c)[1]), "+f"((c)[2]), "+f"((c)[3]) \
                 : "r"((a)[0]), "r"((a)[1]), "r"((a)[2]), "r"((a)[3]), \
                   "r"((b)[0]), "r"((b)[1]))

// split a,b (fp32) -> (hiPair, loPair) packed u32 (2 bf16 each, a in low half)
__device__ __forceinline__ void split2(float a, float b, uint32_t& hp, uint32_t& lp)
{
    __nv_bfloat16 ha = __float2bfloat16_rn(a), hb = __float2bfloat16_rn(b);
    float ra = a - __bfloat162float(ha), rb = b - __bfloat162float(hb);
    __nv_bfloat16 la = __float2bfloat16_rn(ra), lb = __float2bfloat16_rn(rb);
    hp = (uint32_t)__bfloat16_as_ushort(ha) | ((uint32_t)__bfloat16_as_ushort(hb) << 16);
    lp = (uint32_t)__bfloat16_as_ushort(la) | ((uint32_t)__bfloat16_as_ushort(lb) << 16);
}
__device__ __forceinline__ float2 bf2_to_f2(uint32_t u)
{
    __nv_bfloat162 v = *(__nv_bfloat162*)&u;
    return __bfloat1622float2(v);
}

// ---------------------------------------------------------------------------
// int64 vs int32 edge-index detection
// ---------------------------------------------------------------------------
__global__ void detect_kernel(const int* __restrict__ ei)
{
    if (threadIdx.x == 0) {
        const long long* e64 = (const long long*)ei;
        int ok = 1;
        #pragma unroll 1
        for (int i = 0; i < 16; i++) {
            long long s = e64[i], d = e64[NE + i];
            if (s < 0 || s >= NN || d < 0 || d >= NN) ok = 0;
        }
        g_idx64 = ok;
    }
}
__device__ __forceinline__ int load_src(const int* ei, int e, int w) {
    return w ? (int)((const long long*)ei)[e] : ei[e];
}
__device__ __forceinline__ int load_dst(const int* ei, int e, int w) {
    return w ? (int)((const long long*)ei)[NE + e] : ei[NE + e];
}

// ---------------------------------------------------------------------------
// pack x / W into bf16 planes
// ---------------------------------------------------------------------------
__global__ void pack_x_kernel(const float* __restrict__ x)
{
    int i = blockIdx.x * blockDim.x + threadIdx.x;     // float4 index
    if (i >= NN * DD / 4) return;
    float4 v = ((const float4*)x)[i];
    uint32_t h0, l0, h1, l1;
    split2(v.x, v.y, h0, l0);
    split2(v.z, v.w, h1, l1);
    ((uint2*)g_xhi)[i] = make_uint2(h0, h1);
    ((uint2*)g_xlo)[i] = make_uint2(l0, l1);
}
__global__ void pack_w_kernel(const float* __restrict__ Wl,
                              const float* __restrict__ Wr,
                              const float* __restrict__ Wp1)
{
    int i = blockIdx.x * blockDim.x + threadIdx.x;     // float4 index
    if (i >= NW * DD * DD / 4) return;
    int mat = i >> 12;                                  // 4096 float4 per matrix
    int within = i & 4095;
    const float* src = (mat < 3) ? (Wl + (size_t)mat * DD * DD)
                     : (mat < 6) ? (Wr + (size_t)(mat - 3) * DD * DD)
                                 : Wp1;
    float4 v = ((const float4*)src)[within];
    uint32_t h0, l0, h1, l1;
    split2(v.x, v.y, h0, l0);
    split2(v.z, v.w, h1, l1);
    ((uint2*)g_whi)[i] = make_uint2(h0, h1);
    ((uint2*)g_wlo)[i] = make_uint2(l0, l1);
}

// ---------------------------------------------------------------------------
// CSR build
// ---------------------------------------------------------------------------
__global__ void zero_deg_kernel()
{
    int i = blockIdx.x * blockDim.x + threadIdx.x;
    if (i < NN) g_deg[i] = 0;
}
__global__ void count_kernel(const int* __restrict__ ei)
{
    int e = blockIdx.x * blockDim.x + threadIdx.x;
    if (e < NE) atomicAdd(&g_deg[load_dst(ei, e, g_idx64)], 1);
}
__global__ void scanA_kernel()
{
    __shared__ int s[256];
    int i = blockIdx.x * 256 + threadIdx.x;
    int v = (i < NN) ? g_deg[i] : 0;
    s[threadIdx.x] = v; __syncthreads();
    for (int d = 128; d > 0; d >>= 1) {
        if (threadIdx.x < d) s[threadIdx.x] += s[threadIdx.x + d];
        __syncthreads();
    }
    if (threadIdx.x == 0) g_bsum[blockIdx.x] = s[0];
}
__global__ void scanB_kernel()
{
    __shared__ int s[512];
    int tid = threadIdx.x;
    int v = (tid < NBLK) ? g_bsum[tid] : 0;
    s[tid] = v; __syncthreads();
    for (int d = 1; d < 512; d <<= 1) {
        int t = (tid >= d) ? s[tid - d] : 0;
        __syncthreads();
        s[tid] += t; __syncthreads();
    }
    if (tid < NBLK) g_boff[tid] = s[tid] - v;
}
__global__ void scanC_kernel()
{
    __shared__ int s[256];
    int i = blockIdx.x * 256 + threadIdx.x;
    int v = (i < NN) ? g_deg[i] : 0;
    s[threadIdx.x] = v; __syncthreads();
    for (int d = 1; d < 256; d <<= 1) {
        int t = (threadIdx.x >= d) ? s[threadIdx.x - d] : 0;
        __syncthreads();
        s[threadIdx.x] += t; __syncthreads();
    }
    if (i < NN) {
        int off = g_boff[blockIdx.x] + s[threadIdx.x] - v;
        g_off[i] = off; g_cur[i] = off;
    }
}
__global__ void fill_kernel(const int* __restrict__ ei)
{
    int e = blockIdx.x * blockDim.x + threadIdx.x;
    if (e < NE) {
        int w = g_idx64;
        int src = load_src(ei, e, w);
        int dst = load_dst(ei, e, w);
        g_csr[atomicAdd(&g_cur[dst], 1)] = src;
    }
}

// ---------------------------------------------------------------------------
// Column-blocked gather: pass `half` aggregates cols [64*half, 64*half+64).
// Per-pass L2 footprint ~58MB (fully resident). Warp per node; lane owns
// 2 columns; reads hi+lo planes (u32 each), accumulates fp32, re-splits.
// ---------------------------------------------------------------------------
__global__ void __launch_bounds__(256)
gather_kernel(const uint16_t* __restrict__ Ahi, const uint16_t* __restrict__ Alo,
              uint16_t* __restrict__ Phi, uint16_t* __restrict__ Plo, int half)
{
    int d    = blockIdx.x * 8 + (threadIdx.x >> 5);
    int lane = threadIdx.x & 31;
    if (d >= NN) return;

    int off = g_off[d], deg = g_deg[d];
    const int colb = half * 64 + lane * 2;              // bf16 element offset in row
    float a0 = 0.f, a1 = 0.f;

    #define ACC(s) {                                                        \
        uint32_t uh = *(const uint32_t*)(Ahi + (size_t)(s) * DD + colb);    \
        uint32_t ul = *(const uint32_t*)(Alo + (size_t)(s) * DD + colb);    \
        float2 hf = bf2_to_f2(uh), lf = bf2_to_f2(ul);                      \
        a0 += hf.x + lf.x; a1 += hf.y + lf.y; }

    int j = 0;
    for (; j + 4 <= deg; j += 4) {
        int s0 = g_csr[off + j],     s1 = g_csr[off + j + 1];
        int s2 = g_csr[off + j + 2], s3 = g_csr[off + j + 3];
        ACC(s0); ACC(s1); ACC(s2); ACC(s3);
    }
    for (; j < deg; j++) { int s0 = g_csr[off + j]; ACC(s0); }
    #undef ACC

    uint32_t hp, lp;
    split2(a0, a1, hp, lp);
    *(uint32_t*)(Phi + (size_t)d * DD + colb) = hp;
    *(uint32_t*)(Plo + (size_t)d * DD + colb) = lp;
}

// ---------------------------------------------------------------------------
// mma.sync bf16 GEMM, 3xBF16 split, plane inputs (pure-copy load phase).
//   TWO:  D = A0@W0^T + A1@W1^T + (b0+b1); NORM -> row-L2-norm+ReLU -> planes
//   else: D = A0@W0^T + b0 -> fp32 outF
// smem rows stride 272B (rotated bank groups, ldmatrix conflict-free).
// ---------------------------------------------------------------------------
#define SM_AHI  0
#define SM_ALO  34816
#define SM_WHI  69632
#define SM_WLO  104448
#define SM_BIAS 139264
#define SM_TOTAL 139776

template<bool TWO, bool NORM>
__global__ void __launch_bounds__(256, 1)
mma_kernel(const uint16_t* __restrict__ Ahi0, const uint16_t* __restrict__ Alo0,
           const uint16_t* __restrict__ Ahi1, const uint16_t* __restrict__ Alo1,
           const uint16_t* __restrict__ Whi0, const uint16_t* __restrict__ Wlo0,
           const uint16_t* __restrict__ Whi1, const uint16_t* __restrict__ Wlo1,
           const float* __restrict__ b0, const float* __restrict__ b1,
           uint16_t* __restrict__ outHi, uint16_t* __restrict__ outLo,
           float* __restrict__ outF)
{
    extern __shared__ char smem[];
    const uint32_t sb = smem_u32(smem);
    const int tid   = threadIdx.x;
    const int lane  = tid & 31;
    const int wid   = tid >> 5;
    const int warpM = wid & 3;
    const int warpN = wid >> 2;
    const int n0    = blockIdx.x * 128;

    float* bsh = (float*)(smem + SM_BIAS);
    if (tid < 128) {
        float b = b0[tid];
        if (TWO) b += b1[tid];
        bsh[tid] = b;
    }

    float acc[2][8][4];
    #pragma unroll
    for (int mt = 0; mt < 2; mt++)
        #pragma unroll
        for (int nt = 0; nt < 8; nt++)
            #pragma unroll
            for (int r = 0; r < 4; r++)
                acc[mt][nt][r] = 0.f;

    const int mat = lane >> 3, r8 = lane & 7;
    const uint32_t aLane = (uint32_t)((warpM * 32 + (mat & 1) * 8 + r8) * 272
                                      + ((mat >> 1) * 8) * 2);
    const uint32_t bLane = (uint32_t)((warpN * 64 + (mat >> 1) * 8 + r8) * 272
                                      + ((mat & 1) * 8) * 2);

    const int NPH = TWO ? 2 : 1;
    #pragma unroll 1
    for (int ph = 0; ph < NPH; ph++) {
        const uint16_t* Ah = (TWO && ph) ? Ahi1 : Ahi0;
        const uint16_t* Al = (TWO && ph) ? Alo1 : Alo0;
        const uint16_t* Wh = (TWO && ph) ? Whi1 : Whi0;
        const uint16_t* Wl = (TWO && ph) ? Wlo1 : Wlo0;

        __syncthreads();
        // ---- pure-copy load of 4 bf16 planes (16B chunks) ----
        #pragma unroll
        for (int it = 0; it < 8; it++) {
            int gi  = tid + it * 256;        // 0..2047
            int row = gi >> 4, c = gi & 15;  // 16 chunks of 16B per 256B row
            int grow = n0 + row;
            size_t gsrc = (size_t)grow * DD + c * 8;   // bf16 element index
            uint32_t dofs = (uint32_t)(row * 272 + c * 16);
            uint4 vh = make_uint4(0,0,0,0), vl = make_uint4(0,0,0,0);
            if (grow < NN) {
                vh = *(const uint4*)(Ah + gsrc);
                vl = *(const uint4*)(Al + gsrc);
            }
            *(uint4*)(smem + SM_AHI + dofs) = vh;
            *(uint4*)(smem + SM_ALO + dofs) = vl;
            size_t wsrc = (size_t)row * DD + c * 8;
            *(uint4*)(smem + SM_WHI + dofs) = *(const uint4*)(Wh + wsrc);
            *(uint4*)(smem + SM_WLO + dofs) = *(const uint4*)(Wl + wsrc);
        }
        __syncthreads();

        // ---- 3 split products (hi*hi, hi*lo, lo*hi) ----
        #pragma unroll 1
        for (int pr = 0; pr < 3; pr++) {
            const uint32_t aBase = sb + ((pr == 2) ? SM_ALO : SM_AHI) + aLane;
            const uint32_t bBase = sb + ((pr == 1) ? SM_WLO : SM_WHI) + bLane;
            #pragma unroll
            for (int ks = 0; ks < 8; ks++) {
                const uint32_t kOff = ks * 32;
                uint32_t af[2][4];
                LDSM4(af[0][0], af[0][1], af[0][2], af[0][3], aBase + kOff);
                LDSM4(af[1][0], af[1][1], af[1][2], af[1][3], aBase + kOff + 16 * 272);
                uint32_t bf[8][2];
                #pragma unroll
                for (int p = 0; p < 4; p++) {
                    LDSM4(bf[2*p][0], bf[2*p][1], bf[2*p+1][0], bf[2*p+1][1],
                          bBase + kOff + p * 16 * 272);
                }
                #pragma unroll
                for (int mt = 0; mt < 2; mt++)
                    #pragma unroll
                    for (int nt = 0; nt < 8; nt++)
                        MMA16816(acc[mt][nt], af[mt], bf[nt]);
            }
        }
    }

    // ---- epilogue: stage fp32 acc in smem, then row-wise pass ----
    __syncthreads();
    float* fbuf = (float*)smem;                 // [128][132] fp32
    {
        int row0 = warpM * 32 + (lane >> 2);
        int col0 = warpN * 64 + (lane & 3) * 2;
        #pragma unroll
        for (int mt = 0; mt < 2; mt++)
            #pragma unroll
            for (int nt = 0; nt < 8; nt++) {
                int r = row0 + mt * 16, c = col0 + nt * 8;
                fbuf[r * 132 + c]           = acc[mt][nt][0];
                fbuf[r * 132 + c + 1]       = acc[mt][nt][1];
                fbuf[(r + 8) * 132 + c]     = acc[mt][nt][2];
                fbuf[(r + 8) * 132 + c + 1] = acc[mt][nt][3];
            }
    }
    __syncthreads();
    {
        int row  = tid >> 1, half = tid & 1;
        int grow = n0 + row;
        const float* frow = fbuf + row * 132 + half * 64;
        const float* brow = bsh + half * 64;
        float inv = 1.0f;
        if (NORM) {
            float ss = 0.f;
            #pragma unroll
            for (int c = 0; c < 64; c++) {
                float v = frow[c] + brow[c];
                ss += v * v;
            }
            ss += __shfl_xor_sync(0xffffffffu, ss, 1);
            inv = 1.0f / fmaxf(sqrtf(ss), 1e-12f);
        }
        if (grow < NN) {
            if (NORM) {
                uint16_t* oh = outHi + (size_t)grow * DD + half * 64;
                uint16_t* ol = outLo + (size_t)grow * DD + half * 64;
                #pragma unroll
                for (int c = 0; c < 64; c += 4) {
                    float4 f = *(const float4*)(frow + c);
                    float4 bv = *(const float4*)(brow + c);
                    f.x = fmaxf((f.x + bv.x) * inv, 0.f);
                    f.y = fmaxf((f.y + bv.y) * inv, 0.f);
                    f.z = fmaxf((f.z + bv.z) * inv, 0.f);
                    f.w = fmaxf((f.w + bv.w) * inv, 0.f);
                    uint32_t h0, l0, h1, l1;
                    split2(f.x, f.y, h0, l0);
                    split2(f.z, f.w, h1, l1);
                    *(uint2*)(oh + c) = make_uint2(h0, h1);
                    *(uint2*)(ol + c) = make_uint2(l0, l1);
                }
            } else {
                float* orow = outF + (size_t)grow * DD + half * 64;
                #pragma unroll
                for (int c = 0; c < 64; c += 4) {
                    float4 f = *(const float4*)(frow + c);
                    float4 bv = *(const float4*)(brow + c);
                    f.x += bv.x; f.y += bv.y; f.z += bv.z; f.w += bv.w;
                    *(float4*)(orow + c) = f;
                }
            }
        }
    }
}

// ---------------------------------------------------------------------------
// post2 + log_softmax (fp32)
// ---------------------------------------------------------------------------
__global__ void __launch_bounds__(256)
post2_kernel(const float* __restrict__ h, const float* __restrict__ W,
             const float* __restrict__ b, float* __restrict__ out)
{
    __shared__ float Ws[DOUT * DD];
    __shared__ float bs[DOUT];
    const int tid = threadIdx.x;
    for (int i = tid; i < DOUT * DD; i += blockDim.x) Ws[i] = W[i];
    if (tid < DOUT) bs[tid] = b[tid];
    __syncthreads();

    int n = blockIdx.x * blockDim.x + tid;
    if (n >= NN) return;

    float acc[DOUT];
    #pragma unroll
    for (int o = 0; o < DOUT; o++) acc[o] = bs[o];

    const float4* row = (const float4*)(h + (size_t)n * DD);
    #pragma unroll 1
    for (int kq = 0; kq < DD / 4; kq++) {
        float4 x = row[kq];
        #pragma unroll
        for (int o = 0; o < DOUT; o++) {
            const float* wr = &Ws[o * DD + kq * 4];
            acc[o] = fmaf(x.x, wr[0], acc[o]);
            acc[o] = fmaf(x.y, wr[1], acc[o]);
            acc[o] = fmaf(x.z, wr[2], acc[o]);
            acc[o] = fmaf(x.w, wr[3], acc[o]);
        }
    }
    float m = acc[0];
    #pragma unroll
    for (int o = 1; o < DOUT; o++) m = fmaxf(m, acc[o]);
    float s = 0.f;
    #pragma unroll
    for (int o = 0; o < DOUT; o++) s += expf(acc[o] - m);
    float ls = logf(s);
    #pragma unroll
    for (int o = 0; o < DOUT; o++)
        out[(size_t)n * DOUT + o] = acc[o] - m - ls;
}

// ---------------------------------------------------------------------------
// Static stream/event resources
// ---------------------------------------------------------------------------
struct GpuRes {
    cudaStream_t s2;
    cudaEvent_t evF, evCSR;
    GpuRes() {
        cudaStreamCreateWithFlags(&s2, cudaStreamNonBlocking);
        cudaEventCreateWithFlags(&evF,  cudaEventDisableTiming);
        cudaEventCreateWithFlags(&evCSR, cudaEventDisableTiming);
    }
};
static GpuRes g_res;

// ---------------------------------------------------------------------------
// Launcher
// ---------------------------------------------------------------------------
extern "C" void kernel_launch(void* const* d_in, const int* in_sizes, int n_in,
                              void* d_out, int out_size)
{
    const float* x   = (const float*)d_in[0];
    const int*   ei  = (const int*)  d_in[1];
    const float* Wl  = (const float*)d_in[2];
    const float* bl  = (const float*)d_in[3];
    const float* Wr  = (const float*)d_in[4];
    const float* br  = (const float*)d_in[5];
    const float* Wp1 = (const float*)d_in[6];
    const float* bp1 = (const float*)d_in[7];
    const float* Wp2 = (const float*)d_in[8];
    const float* bp2 = (const float*)d_in[9];
    float* out = (float*)d_out;

    cudaFuncSetAttribute(mma_kernel<true,  true>,
                         cudaFuncAttributeMaxDynamicSharedMemorySize, SM_TOTAL);
    cudaFuncSetAttribute(mma_kernel<false, false>,
                         cudaFuncAttributeMaxDynamicSharedMemorySize, SM_TOTAL);

    uint16_t *xhi, *xlo, *hhi, *hlo, *phi, *plo, *whi, *wlo;
    float* tmp;
    cudaGetSymbolAddress((void**)&xhi, g_xhi);
    cudaGetSymbolAddress((void**)&xlo, g_xlo);
    cudaGetSymbolAddress((void**)&hhi, g_hhi);
    cudaGetSymbolAddress((void**)&hlo, g_hlo);
    cudaGetSymbolAddress((void**)&phi, g_phi);
    cudaGetSymbolAddress((void**)&plo, g_plo);
    cudaGetSymbolAddress((void**)&whi, g_whi);
    cudaGetSymbolAddress((void**)&wlo, g_wlo);
    cudaGetSymbolAddress((void**)&tmp, g_tmp);

    cudaStream_t s0 = 0, s2 = g_res.s2;

    detect_kernel<<<1, 1, 0, s0>>>(ei);
    cudaEventRecord(g_res.evF, s0);
    cudaStreamWaitEvent(s2, g_res.evF, 0);

    // CSR build on s2; packs on s0 (overlapped)
    zero_deg_kernel<<<NBLK, 256, 0, s2>>>();
    count_kernel<<<(NE + 255) / 256, 256, 0, s2>>>(ei);
    scanA_kernel<<<NBLK, 256, 0, s2>>>();
    scanB_kernel<<<1, 512, 0, s2>>>();
    scanC_kernel<<<NBLK, 256, 0, s2>>>();
    fill_kernel<<<(NE + 255) / 256, 256, 0, s2>>>(ei);
    cudaEventRecord(g_res.evCSR, s2);

    pack_x_kernel<<<(NN * DD / 4 + 255) / 256, 256, 0, s0>>>(x);
    pack_w_kernel<<<(NW * DD * DD / 4 + 255) / 256, 256, 0, s0>>>(Wl, Wr, Wp1);
    cudaStreamWaitEvent(s0, g_res.evCSR, 0);

    const int GGB = (NN + 7) / 8;
    const size_t WSZ = (size_t)DD * DD;
    for (int l = 0; l < NLAYERS; l++) {
        const uint16_t* ahi = (l == 0) ? xhi : hhi;
        const uint16_t* alo = (l == 0) ? xlo : hlo;
        gather_kernel<<<GGB, 256, 0, s0>>>(ahi, alo, phi, plo, 0);
        gather_kernel<<<GGB, 256, 0, s0>>>(ahi, alo, phi, plo, 1);
        mma_kernel<true, true><<<GTILES, 256, SM_TOTAL, s0>>>(
            ahi, alo, phi, plo,
            whi + (size_t)l * WSZ,       wlo + (size_t)l * WSZ,
            whi + (size_t)(3 + l) * WSZ, wlo + (size_t)(3 + l) * WSZ,
            bl + (size_t)l * DD, br + (size_t)l * DD,
            hhi, hlo, nullptr);
    }

    // post1 -> fp32 tmp, then post2 + log_softmax -> out
    mma_kernel<false, false><<<GTILES, 256, SM_TOTAL, s0>>>(
        hhi, hlo, nullptr, nullptr,
        whi + (size_t)6 * WSZ, wlo + (size_t)6 * WSZ, nullptr, nullptr,
        bp1, nullptr, nullptr, nullptr, tmp);
    post2_kernel<<<NBLK, 256, 0, s0>>>(tmp, Wp2, bp2, out);
}